// round 15
// baseline (speedup 1.0000x reference)
#include <cuda_runtime.h>
#include <cuda_fp16.h>
#include <math.h>

#define D_MODEL 512
#define N_HEADS 8
#define HEAD_E  64
#define D_FF    2048
#define BATCH   4
#define SEQ     2048
#define M_ROWS  (BATCH*SEQ)   /* 8192 */
#define LOG2E   1.4426950408889634f

// ---------------- scratch (device globals: allocation-guard safe) ----------
__device__ __half g_xh  [M_ROWS * D_MODEL];
__device__ __half g_qh  [M_ROWS * D_MODEL];
__device__ __half g_kh  [M_ROWS * D_MODEL];   // pre-scaled by log2e
__device__ __half g_vt  [BATCH * D_MODEL * SEQ];   // [b][col][l] transposed
__device__ __half g_ah  [M_ROWS * D_MODEL];
__device__ __half g_h16 [M_ROWS * D_FF];
__device__ __half g_x1h [M_ROWS * D_MODEL];
__device__ float  g_x1  [M_ROWS * D_MODEL];
__device__ __half g_wqkv[3 * D_MODEL * D_MODEL];   // [1536][512] transposed
__device__ __half g_wot [D_MODEL * D_MODEL];
__device__ __half g_w1t [D_FF * D_MODEL];
__device__ __half g_w2t [D_MODEL * D_FF];
__device__ float  g_bqkv[3 * D_MODEL];

// ---------------- helpers ----------------------------------------------------
__device__ __forceinline__ unsigned sptr(const void* p) {
    return (unsigned)__cvta_generic_to_shared(p);
}
__device__ __forceinline__ void cp16(const void* dst, const void* src) {
    asm volatile("cp.async.cg.shared.global [%0], [%1], 16;"
                 :: "r"(sptr(dst)), "l"(src));
}
#define CP_COMMIT() asm volatile("cp.async.commit_group;")
#define CP_WAIT0()  asm volatile("cp.async.wait_group 0;")
#define CP_WAIT1()  asm volatile("cp.async.wait_group 1;")

__device__ __forceinline__ unsigned pack_h2(float lo, float hi) {
    unsigned r;
    asm("cvt.rn.f16x2.f32 %0, %1, %2;" : "=r"(r) : "f"(hi), "f"(lo));
    return r;
}
__device__ __forceinline__ unsigned ex2_h2(unsigned a) {
    unsigned r;
    asm("ex2.approx.f16x2 %0, %1;" : "=r"(r) : "r"(a));
    return r;
}
__device__ __forceinline__ void mma16(float* c, const unsigned* a,
                                      unsigned b0, unsigned b1) {
    asm volatile(
        "mma.sync.aligned.m16n8k16.row.col.f32.f16.f16.f32 "
        "{%0,%1,%2,%3},{%4,%5,%6,%7},{%8,%9},{%0,%1,%2,%3};"
        : "+f"(c[0]), "+f"(c[1]), "+f"(c[2]), "+f"(c[3])
        : "r"(a[0]), "r"(a[1]), "r"(a[2]), "r"(a[3]), "r"(b0), "r"(b1));
}
__device__ __forceinline__ void ldsm4(unsigned* r, unsigned a) {
    asm volatile("ldmatrix.sync.aligned.m8n8.x4.shared.b16 {%0,%1,%2,%3}, [%4];"
                 : "=r"(r[0]), "=r"(r[1]), "=r"(r[2]), "=r"(r[3]) : "r"(a));
}
__device__ __forceinline__ float gelu_exact(float v) {
    return 0.5f * v * (1.0f + erff(v * 0.70710678118654752f));
}

// ---------------- merged prep kernel -----------------------------------------
__device__ __forceinline__ void do_transpose(const float* __restrict__ in,
                                             __half* __restrict__ out,
                                             int K, int N, int k0, int n0, int tid)
{
    __shared__ float tile[32][33];
    const int tx = tid & 31, ty = tid >> 5;
    #pragma unroll
    for (int i = 0; i < 32; i += 8)
        tile[ty + i][tx] = in[(size_t)(k0 + ty + i) * N + n0 + tx];
    __syncthreads();
    #pragma unroll
    for (int i = 0; i < 32; i += 8)
        out[(size_t)(n0 + ty + i) * K + k0 + tx] = __float2half(tile[tx][ty + i]);
}

__global__ void __launch_bounds__(256)
prep_kernel(const float* x, const float* Wq, const float* Wk, const float* Wv,
            const float* Wo, const float* W1, const float* W2,
            const float* bq, const float* bk, const float* bv,
            __half* xh, __half* wqkv, __half* wot, __half* w1t, __half* w2t,
            float* bqkv)
{
    const int blk = blockIdx.x;
    const int tid = threadIdx.x;
    if (blk < 1024) {
        const int z = blk >> 8, t = blk & 255;
        const float* in = (z == 0) ? Wq : (z == 1) ? Wk : (z == 2) ? Wv : Wo;
        __half* out = (z == 3) ? wot : (wqkv + (size_t)z * D_MODEL * D_MODEL);
        do_transpose(in, out, D_MODEL, D_MODEL, (t >> 4) * 32, (t & 15) * 32, tid);
    } else if (blk < 2048) {
        const int t = blk - 1024;
        do_transpose(W1, w1t, D_MODEL, D_FF, (t >> 6) * 32, (t & 63) * 32, tid);
    } else if (blk < 3072) {
        const int t = blk - 2048;
        do_transpose(W2, w2t, D_FF, D_MODEL, (t >> 4) * 32, (t & 15) * 32, tid);
    } else if (blk < 7168) {
        const int i = ((blk - 3072) * 256 + tid) * 4;
        float4 v = *(const float4*)&x[i];
        *(uint2*)&xh[i] = make_uint2(pack_h2(v.x, v.y), pack_h2(v.z, v.w));
    } else {
        const int i = (blk - 7168) * 256 + tid;
        if (i < D_MODEL) {
            bqkv[i] = bq[i];
            bqkv[D_MODEL + i] = bk[i];
            bqkv[2 * D_MODEL + i] = bv[i];
        }
    }
}

// ---------------- fp16 GEMM (mma.sync + ldmatrix, BK=32, 3-stage) ------------
// C[M,N] = A[M,K] @ Bt[N,K]^T + bias.
// OUT: 1 fp16 row-major, 3 QKV split epilogue (k scaled by log2e)
#define GS    20
#define GBUF  (128 * GS)
#define GEMM_SMEM (6 * GBUF * 4)

template<int ACT, int OUT>
__global__ void __launch_bounds__(256, 2)
mma_gemm(const __half* __restrict__ A, const __half* __restrict__ Bt,
         const float* __restrict__ bias, void* Cv, void* Cv2, void* Cv3,
         int K, int N)
{
    extern __shared__ unsigned smu[];
    const unsigned sb = sptr(smu);

    const int tid  = threadIdx.x;
    const int warp = tid >> 5, lane = tid & 31;
    const int wm   = warp >> 1, wn = warp & 1;
    const int lr   = lane >> 2, lc = lane & 3;
    const int m8   = lane >> 3, j8 = lane & 7;
    const int m0   = blockIdx.y * 128;
    const int n0   = blockIdx.x * 128;

    const int row = tid >> 1;
    const int hf  = tid & 1;

    unsigned aoff[2], boff[4];
    #pragma unroll
    for (int tm = 0; tm < 2; tm++)
        aoff[tm] = (unsigned)((wm * 32 + tm * 16 + (m8 & 1) * 8 + j8) * (GS * 4)
                              + (m8 >> 1) * 16);
    #pragma unroll
    for (int tnp = 0; tnp < 4; tnp++)
        boff[tnp] = (unsigned)((wn * 64 + tnp * 16 + (m8 >> 1) * 8 + j8) * (GS * 4)
                               + (m8 & 1) * 16);

    float acc[2][8][4];
    #pragma unroll
    for (int i = 0; i < 2; i++)
        #pragma unroll
        for (int j = 0; j < 8; j++)
            #pragma unroll
            for (int r = 0; r < 4; r++) acc[i][j][r] = 0.0f;

    const int KT = K >> 5;

    auto issue = [&](int kt, int buf) {
        const __half* sa = A  + (size_t)(m0 + row) * K + (kt << 5) + (hf << 4);
        unsigned* da = smu + buf * GBUF + row * GS + (hf << 3);
        cp16(da,     sa);
        cp16(da + 4, sa + 8);
        const __half* sbp = Bt + (size_t)(n0 + row) * K + (kt << 5) + (hf << 4);
        unsigned* db = smu + (3 + buf) * GBUF + row * GS + (hf << 3);
        cp16(db,     sbp);
        cp16(db + 4, sbp + 8);
    };

    issue(0, 0);
    CP_COMMIT();
    if (KT > 1) { issue(1, 1); CP_COMMIT(); }

    int bufc = 0;
    for (int kt = 0; kt < KT; kt++) {
        if (kt + 1 < KT) CP_WAIT1(); else CP_WAIT0();
        __syncthreads();
        if (kt + 2 < KT) {
            int nb = bufc + 2; if (nb >= 3) nb -= 3;
            issue(kt + 2, nb);
            CP_COMMIT();
        }

        const unsigned aB = sb + bufc * (GBUF * 4);
        const unsigned bB = sb + (3 + bufc) * (GBUF * 4);

        #pragma unroll
        for (int ks = 0; ks < 2; ks++) {
            unsigned af[2][4];
            ldsm4(af[0], aB + aoff[0] + ks * 32);
            ldsm4(af[1], aB + aoff[1] + ks * 32);
            #pragma unroll
            for (int tnp = 0; tnp < 4; tnp++) {
                unsigned bf[4];
                ldsm4(bf, bB + boff[tnp] + ks * 32);
                mma16(acc[0][2 * tnp],     af[0], bf[0], bf[1]);
                mma16(acc[1][2 * tnp],     af[1], bf[0], bf[1]);
                mma16(acc[0][2 * tnp + 1], af[0], bf[2], bf[3]);
                mma16(acc[1][2 * tnp + 1], af[1], bf[2], bf[3]);
            }
        }
        bufc = (bufc == 2) ? 0 : bufc + 1;
    }

    // epilogue
    #pragma unroll
    for (int tm = 0; tm < 2; tm++) {
        #pragma unroll
        for (int tn = 0; tn < 8; tn++) {
            const int rw  = m0 + wm * 32 + tm * 16 + lr;
            const int col = n0 + wn * 64 + tn * 8 + 2 * lc;
            const float b0 = bias[col], b1 = bias[col + 1];
            float2 v0 = make_float2(acc[tm][tn][0] + b0, acc[tm][tn][1] + b1);
            float2 v1 = make_float2(acc[tm][tn][2] + b0, acc[tm][tn][3] + b1);
            if (ACT) {
                v0.x = gelu_exact(v0.x); v0.y = gelu_exact(v0.y);
                v1.x = gelu_exact(v1.x); v1.y = gelu_exact(v1.y);
            }
            if (OUT == 1) {
                __half* C = (__half*)Cv;
                *(unsigned*)&C[(size_t)rw * N + col]       = pack_h2(v0.x, v0.y);
                *(unsigned*)&C[(size_t)(rw + 8) * N + col] = pack_h2(v1.x, v1.y);
            } else {
                if (col < 1024) {
                    __half* C = (__half*)(col < 512 ? Cv : Cv2);
                    if (col >= 512) {   // k segment: fold log2e into k
                        v0.x *= LOG2E; v0.y *= LOG2E;
                        v1.x *= LOG2E; v1.y *= LOG2E;
                    }
                    const int c = col & 511;
                    *(unsigned*)&C[(size_t)rw * D_MODEL + c]       = pack_h2(v0.x, v0.y);
                    *(unsigned*)&C[(size_t)(rw + 8) * D_MODEL + c] = pack_h2(v1.x, v1.y);
                } else {
                    __half* C = (__half*)Cv3;
                    const int c  = col - 1024;
                    const int bb = rw >> 11, ll = rw & 2047;
                    C[((size_t)(bb * D_MODEL + c))     * SEQ + ll]     = __float2half(v0.x);
                    C[((size_t)(bb * D_MODEL + c + 1)) * SEQ + ll]     = __float2half(v0.y);
                    C[((size_t)(bb * D_MODEL + c))     * SEQ + ll + 8] = __float2half(v1.x);
                    C[((size_t)(bb * D_MODEL + c + 1)) * SEQ + ll + 8] = __float2half(v1.y);
                }
            }
        }
    }
}

// ---------------- fused GEMM + residual + LayerNorm --------------------------
// out = LN(xres + A @ Bt^T + bias)  for N = 512 exactly.
// BM=32, BN=512, BK=32, 256 threads = 8 warps (warp wn owns cols [wn*64,+64)).
// 2-stage cp.async pipeline; epilogue does the row reduction in-register.
#define LGS      20
#define LG_ABUF  (32 * LGS)           /* A stage: 640 words */
#define LG_BBUF  (512 * LGS)          /* B stage: 10240 words */
#define LG_STAGE (LG_ABUF + LG_BBUF)
#define LNGEMM_SMEM (2 * LG_STAGE * 4)

template<int W16>
__global__ void __launch_bounds__(256, 2)
ln_gemm(const __half* __restrict__ A, const __half* __restrict__ Bt,
        const float* __restrict__ bias, const float* __restrict__ xres,
        const float* __restrict__ gam, const float* __restrict__ bet,
        float* __restrict__ Out, __half* __restrict__ Out16, int K)
{
    extern __shared__ unsigned smu[];
    const unsigned sb = sptr(smu);

    const int tid  = threadIdx.x;
    const int wn   = tid >> 5, lane = tid & 31;
    const int lr   = lane >> 2, lc = lane & 3;
    const int m8   = lane >> 3, j8 = lane & 7;
    const int m0   = blockIdx.x * 32;

    unsigned aoff[2], boff[4];
    #pragma unroll
    for (int tm = 0; tm < 2; tm++)
        aoff[tm] = (unsigned)((tm * 16 + (m8 & 1) * 8 + j8) * (LGS * 4)
                              + (m8 >> 1) * 16);
    #pragma unroll
    for (int tnp = 0; tnp < 4; tnp++)
        boff[tnp] = (unsigned)((wn * 64 + tnp * 16 + (m8 >> 1) * 8 + j8) * (LGS * 4)
                               + (m8 & 1) * 16);

    float acc[2][8][4];
    #pragma unroll
    for (int i = 0; i < 2; i++)
        #pragma unroll
        for (int j = 0; j < 8; j++)
            #pragma unroll
            for (int r = 0; r < 4; r++) acc[i][j][r] = 0.0f;

    const int KT = K >> 5;

    auto issue = [&](int kt, int buf) {
        const int kk = kt << 5;
        // A: 32 rows x 32 halves (first 128 threads, 1 cp16 each)
        if (tid < 128) {
            const int ar = tid >> 2, ac = tid & 3;
            cp16(smu + buf * LG_STAGE + ar * LGS + ac * 4,
                 A + (size_t)(m0 + ar) * K + kk + ac * 8);
        }
        // B: 512 rows x 32 halves (2 rows/thread, 4 cp16 per row)
        unsigned* bs = smu + buf * LG_STAGE + LG_ABUF;
        #pragma unroll
        for (int rr = 0; rr < 2; rr++) {
            const int r = tid + rr * 256;
            const __half* src = Bt + (size_t)r * K + kk;
            unsigned* dst = bs + r * LGS;
            cp16(dst,      src);
            cp16(dst + 4,  src + 8);
            cp16(dst + 8,  src + 16);
            cp16(dst + 12, src + 24);
        }
    };

    issue(0, 0);
    CP_COMMIT();

    for (int kt = 0; kt < KT; kt++) {
        const int buf = kt & 1;
        CP_WAIT0();
        __syncthreads();
        if (kt + 1 < KT) { issue(kt + 1, buf ^ 1); CP_COMMIT(); }

        const unsigned aB = sb + buf * (LG_STAGE * 4);
        const unsigned bB = aB + LG_ABUF * 4;

        #pragma unroll
        for (int ks = 0; ks < 2; ks++) {
            unsigned af[2][4];
            ldsm4(af[0], aB + aoff[0] + ks * 32);
            ldsm4(af[1], aB + aoff[1] + ks * 32);
            #pragma unroll
            for (int tnp = 0; tnp < 4; tnp++) {
                unsigned bf[4];
                ldsm4(bf, bB + boff[tnp] + ks * 32);
                mma16(acc[0][2 * tnp],     af[0], bf[0], bf[1]);
                mma16(acc[1][2 * tnp],     af[1], bf[0], bf[1]);
                mma16(acc[0][2 * tnp + 1], af[0], bf[2], bf[3]);
                mma16(acc[1][2 * tnp + 1], af[1], bf[2], bf[3]);
            }
        }
        __syncthreads();
    }

    // ---- epilogue: residual add + LayerNorm over full rows -----------------
    // thread's rows: lr, lr+8 (tm=0), lr+16, lr+24 (tm=1); 16 cols each.
    float s[4] = {0, 0, 0, 0}, q[4] = {0, 0, 0, 0};
    const float* Xr = xres + (size_t)m0 * D_MODEL;
    #pragma unroll
    for (int tm = 0; tm < 2; tm++) {
        #pragma unroll
        for (int tn = 0; tn < 8; tn++) {
            const int col = wn * 64 + tn * 8 + 2 * lc;
            const float b0 = bias[col], b1 = bias[col + 1];
            const int r0 = tm * 16 + lr, r1 = r0 + 8;
            float2 xa = *(const float2*)&Xr[(size_t)r0 * D_MODEL + col];
            float2 xb = *(const float2*)&Xr[(size_t)r1 * D_MODEL + col];
            float t0 = acc[tm][tn][0] + b0 + xa.x;
            float t1 = acc[tm][tn][1] + b1 + xa.y;
            float t2 = acc[tm][tn][2] + b0 + xb.x;
            float t3 = acc[tm][tn][3] + b1 + xb.y;
            acc[tm][tn][0] = t0; acc[tm][tn][1] = t1;
            acc[tm][tn][2] = t2; acc[tm][tn][3] = t3;
            s[tm * 2]     += t0 + t1;  q[tm * 2]     += t0 * t0 + t1 * t1;
            s[tm * 2 + 1] += t2 + t3;  q[tm * 2 + 1] += t2 * t2 + t3 * t3;
        }
    }
    #pragma unroll
    for (int i = 0; i < 4; i++) {
        s[i] += __shfl_xor_sync(0xFFFFFFFFu, s[i], 1);
        s[i] += __shfl_xor_sync(0xFFFFFFFFu, s[i], 2);
        q[i] += __shfl_xor_sync(0xFFFFFFFFu, q[i], 1);
        q[i] += __shfl_xor_sync(0xFFFFFFFFu, q[i], 2);
    }

    float* redS = (float*)smu;          // [32][8]
    float* redQ = redS + 32 * 8;        // [32][8]
    float* muv  = redQ + 32 * 8;        // [32]
    float* rsv  = muv + 32;             // [32]
    __syncthreads();                    // smem buffers dead; safe to reuse
    if (lc == 0) {
        #pragma unroll
        for (int i = 0; i < 4; i++) {
            const int r = ((i >> 1) << 4) + ((i & 1) << 3) + lr;  // lr,lr+8,lr+16,lr+24
            redS[r * 8 + wn] = s[i];
            redQ[r * 8 + wn] = q[i];
        }
    }
    __syncthreads();
    if (tid < 32) {
        float ss = 0.0f, qq = 0.0f;
        #pragma unroll
        for (int w = 0; w < 8; w++) { ss += redS[tid * 8 + w]; qq += redQ[tid * 8 + w]; }
        const float mu  = ss * (1.0f / D_MODEL);
        const float var = qq * (1.0f / D_MODEL) - mu * mu;
        muv[tid] = mu;
        rsv[tid] = rsqrtf(var + 1e-5f);
    }
    __syncthreads();

    #pragma unroll
    for (int tm = 0; tm < 2; tm++) {
        #pragma unroll
        for (int tn = 0; tn < 8; tn++) {
            const int col = wn * 64 + tn * 8 + 2 * lc;
            const int r0 = tm * 16 + lr, r1 = r0 + 8;
            const float g0 = gam[col], g1 = gam[col + 1];
            const float e0 = bet[col], e1 = bet[col + 1];
            const float mu0 = muv[r0], rs0 = rsv[r0];
            const float mu1 = muv[r1], rs1 = rsv[r1];
            float2 o0 = make_float2((acc[tm][tn][0] - mu0) * rs0 * g0 + e0,
                                    (acc[tm][tn][1] - mu0) * rs0 * g1 + e1);
            float2 o1 = make_float2((acc[tm][tn][2] - mu1) * rs1 * g0 + e0,
                                    (acc[tm][tn][3] - mu1) * rs1 * g1 + e1);
            *(float2*)&Out[(size_t)(m0 + r0) * D_MODEL + col] = o0;
            *(float2*)&Out[(size_t)(m0 + r1) * D_MODEL + col] = o1;
            if (W16) {
                *(unsigned*)&Out16[(size_t)(m0 + r0) * D_MODEL + col] = pack_h2(o0.x, o0.y);
                *(unsigned*)&Out16[(size_t)(m0 + r1) * D_MODEL + col] = pack_h2(o1.x, o1.y);
            }
        }
    }
}

// ---------------- fused flash attention (h2 exp softmax) ---------------------
#define FKV_STRIDE 36
#define FKV_BUF    (64 * FKV_STRIDE)
#define FLASH_SMEM (6 * FKV_BUF * 4)

__global__ void __launch_bounds__(256, 2)
flash_kernel(const __half* __restrict__ Qh, const __half* __restrict__ Kh,
             const __half* __restrict__ Vt, __half* __restrict__ Oh)
{
    extern __shared__ unsigned smu[];
    const unsigned sb = sptr(smu);

    const int tid  = threadIdx.x;
    const int warp = tid >> 5, lane = tid & 31;
    const int lr   = lane >> 2, lc = lane & 3;
    const int m8   = lane >> 3, j8 = lane & 7;
    const int bh   = blockIdx.y;
    const int b    = bh >> 3, h = bh & 7;
    const int ql0  = blockIdx.x * 128;

    const __half* Qb = Qh + ((size_t)(b * SEQ + ql0)) * D_MODEL + h * HEAD_E;
    const __half* Kb = Kh + ((size_t)(b * SEQ)) * D_MODEL + h * HEAD_E;
    const __half* Vb = Vt + ((size_t)(b * D_MODEL + h * HEAD_E)) * SEQ;

    unsigned qf[4][4];
    {
        const __half2 s8 = __half2half2(__float2half(0.125f));
        const __half* q0 = Qb + (size_t)(warp * 16 + lr) * D_MODEL;
        const __half* q1 = q0 + 8 * D_MODEL;
        #pragma unroll
        for (int ks = 0; ks < 4; ks++) {
            const int e0 = ks * 16 + 2 * lc;
            __half2 t;
            t = __hmul2(*(const __half2*)(q0 + e0), s8);     qf[ks][0] = *(unsigned*)&t;
            t = __hmul2(*(const __half2*)(q1 + e0), s8);     qf[ks][1] = *(unsigned*)&t;
            t = __hmul2(*(const __half2*)(q0 + e0 + 8), s8); qf[ks][2] = *(unsigned*)&t;
            t = __hmul2(*(const __half2*)(q1 + e0 + 8), s8); qf[ks][3] = *(unsigned*)&t;
        }
    }

    unsigned kvoff[4];
    #pragma unroll
    for (int tnp = 0; tnp < 4; tnp++)
        kvoff[tnp] = (unsigned)((tnp * 16 + (m8 >> 1) * 8 + j8) * (FKV_STRIDE * 4)
                                + (m8 & 1) * 16);

    const int lrow = tid >> 2;
    const int lch  = (tid & 3) << 1;
    auto issue = [&](int t, int buf) {
        const int s0 = t << 6;
        unsigned* Kd = smu + buf * FKV_BUF + lrow * FKV_STRIDE + lch * 4;
        const __half* ksrc = Kb + (size_t)(s0 + lrow) * D_MODEL + lch * 8;
        cp16(Kd,     ksrc);
        cp16(Kd + 4, ksrc + 8);
        unsigned* Vd = smu + (3 + buf) * FKV_BUF + lrow * FKV_STRIDE + lch * 4;
        const __half* vsrc = Vb + (size_t)lrow * SEQ + s0 + lch * 8;
        cp16(Vd,     vsrc);
        cp16(Vd + 4, vsrc + 8);
    };

    float oacc[8][4];
    #pragma unroll
    for (int t = 0; t < 8; t++)
        #pragma unroll
        for (int r = 0; r < 4; r++) oacc[t][r] = 0.0f;
    float ls0 = 0.0f, ls1 = 0.0f;

    const int NT = SEQ / 64;
    issue(0, 0);
    CP_COMMIT();
    issue(1, 1);
    CP_COMMIT();

    int bufc = 0;
    for (int t = 0; t < NT; t++) {
        if (t + 1 < NT) CP_WAIT1(); else CP_WAIT0();
        __syncthreads();
        if (t + 2 < NT) {
            int nb = bufc + 2; if (nb >= 3) nb -= 3;
            issue(t + 2, nb);
            CP_COMMIT();
        }

        const unsigned kB = sb + bufc * (FKV_BUF * 4);
        const unsigned vB = sb + (3 + bufc) * (FKV_BUF * 4);

        float sacc[8][4];
        #pragma unroll
        for (int tn = 0; tn < 8; tn++)
            #pragma unroll
            for (int r = 0; r < 4; r++) sacc[tn][r] = 0.0f;
        #pragma unroll
        for (int ks = 0; ks < 4; ks++) {
            #pragma unroll
            for (int tnp = 0; tnp < 4; tnp++) {
                unsigned bf[4];
                ldsm4(bf, kB + kvoff[tnp] + ks * 32);
                mma16(sacc[2 * tnp],     qf[ks], bf[0], bf[1]);
                mma16(sacc[2 * tnp + 1], qf[ks], bf[2], bf[3]);
            }
        }

        unsigned pk0[8], pk1[8];
        #pragma unroll
        for (int tn = 0; tn < 8; tn++) {
            pk0[tn] = ex2_h2(pack_h2(sacc[tn][0], sacc[tn][1]));
            pk1[tn] = ex2_h2(pack_h2(sacc[tn][2], sacc[tn][3]));
        }
        __half2 a0 = __half2half2(__float2half(0.0f));
        __half2 a1 = a0;
        #pragma unroll
        for (int tn = 0; tn < 8; tn++) {
            a0 = __hadd2(a0, *(const __half2*)&pk0[tn]);
            a1 = __hadd2(a1, *(const __half2*)&pk1[tn]);
        }
        float2 f0 = __half22float2(a0);
        float2 f1 = __half22float2(a1);
        float ps0 = f0.x + f0.y;
        float ps1 = f1.x + f1.y;
        ps0 += __shfl_xor_sync(0xFFFFFFFFu, ps0, 1);
        ps0 += __shfl_xor_sync(0xFFFFFFFFu, ps0, 2);
        ps1 += __shfl_xor_sync(0xFFFFFFFFu, ps1, 1);
        ps1 += __shfl_xor_sync(0xFFFFFFFFu, ps1, 2);
        ls0 += ps0;
        ls1 += ps1;

        #pragma unroll
        for (int ks = 0; ks < 4; ks++) {
            unsigned af[4];
            af[0] = pk0[2 * ks];
            af[1] = pk1[2 * ks];
            af[2] = pk0[2 * ks + 1];
            af[3] = pk1[2 * ks + 1];
            #pragma unroll
            for (int tnp = 0; tnp < 4; tnp++) {
                unsigned bf[4];
                ldsm4(bf, vB + kvoff[tnp] + ks * 32);
                mma16(oacc[2 * tnp],     af, bf[0], bf[1]);
                mma16(oacc[2 * tnp + 1], af, bf[2], bf[3]);
            }
        }
        bufc = (bufc == 2) ? 0 : bufc + 1;
    }

    const float inv0 = 1.0f / ls0, inv1 = 1.0f / ls1;
    __half* O0 = Oh + ((size_t)(b * SEQ + ql0 + warp * 16 + lr)) * D_MODEL + h * HEAD_E;
    __half* O1 = O0 + 8 * D_MODEL;
    #pragma unroll
    for (int tn = 0; tn < 8; tn++) {
        const int col = tn * 8 + 2 * lc;
        *(unsigned*)&O0[col] = pack_h2(oacc[tn][0] * inv0, oacc[tn][1] * inv0);
        *(unsigned*)&O1[col] = pack_h2(oacc[tn][2] * inv1, oacc[tn][3] * inv1);
    }
}

// ---------------- launcher --------------------------------------------------
extern "C" void kernel_launch(void* const* d_in, const int* in_sizes, int n_in,
                              void* d_out, int out_size)
{
    const float* x   = (const float*)d_in[0];
    const float* Wq  = (const float*)d_in[1];
    const float* bq  = (const float*)d_in[2];
    const float* Wk  = (const float*)d_in[3];
    const float* bk  = (const float*)d_in[4];
    const float* Wv  = (const float*)d_in[5];
    const float* bv  = (const float*)d_in[6];
    const float* Wo  = (const float*)d_in[7];
    const float* bo  = (const float*)d_in[8];
    const float* W1  = (const float*)d_in[9];
    const float* b1  = (const float*)d_in[10];
    const float* W2  = (const float*)d_in[11];
    const float* b2  = (const float*)d_in[12];
    const float* g1  = (const float*)d_in[13];
    const float* be1 = (const float*)d_in[14];
    const float* g2  = (const float*)d_in[15];
    const float* be2 = (const float*)d_in[16];
    float* out = (float*)d_out;

    __half *xh, *qh, *kh, *vt, *ah, *h16, *x1h, *wqkv, *wot, *w1t, *w2t;
    float *x1, *bqkv;
    cudaGetSymbolAddress((void**)&xh,   g_xh);
    cudaGetSymbolAddress((void**)&qh,   g_qh);
    cudaGetSymbolAddress((void**)&kh,   g_kh);
    cudaGetSymbolAddress((void**)&vt,   g_vt);
    cudaGetSymbolAddress((void**)&ah,   g_ah);
    cudaGetSymbolAddress((void**)&h16,  g_h16);
    cudaGetSymbolAddress((void**)&x1h,  g_x1h);
    cudaGetSymbolAddress((void**)&wqkv, g_wqkv);
    cudaGetSymbolAddress((void**)&wot,  g_wot);
    cudaGetSymbolAddress((void**)&w1t,  g_w1t);
    cudaGetSymbolAddress((void**)&w2t,  g_w2t);
    cudaGetSymbolAddress((void**)&x1,   g_x1);
    cudaGetSymbolAddress((void**)&bqkv, g_bqkv);

    cudaFuncSetAttribute((const void*)mma_gemm<0,3>,
                         cudaFuncAttributeMaxDynamicSharedMemorySize, GEMM_SMEM);
    cudaFuncSetAttribute((const void*)mma_gemm<1,1>,
                         cudaFuncAttributeMaxDynamicSharedMemorySize, GEMM_SMEM);
    cudaFuncSetAttribute((const void*)ln_gemm<0>,
                         cudaFuncAttributeMaxDynamicSharedMemorySize, LNGEMM_SMEM);
    cudaFuncSetAttribute((const void*)ln_gemm<1>,
                         cudaFuncAttributeMaxDynamicSharedMemorySize, LNGEMM_SMEM);
    cudaFuncSetAttribute((const void*)flash_kernel,
                         cudaFuncAttributeMaxDynamicSharedMemorySize, FLASH_SMEM);

    // ---- prep (single merged launch) ----
    prep_kernel<<<7170, 256>>>(x, Wq, Wk, Wv, Wo, W1, W2, bq, bk, bv,
                               xh, wqkv, wot, w1t, w2t, bqkv);

    // ---- fused QKV projection (k pre-scaled by log2e in epilogue) ----
    mma_gemm<0,3><<<dim3(12, M_ROWS / 128), 256, GEMM_SMEM>>>(
        xh, wqkv, bqkv, qh, kh, vt, D_MODEL, 3 * D_MODEL);

    // ---- flash attention ----
    flash_kernel<<<dim3(SEQ / 128, BATCH * N_HEADS), 256, FLASH_SMEM>>>(qh, kh, vt, ah);

    // ---- output projection + residual + LN1 (fused) ----
    ln_gemm<1><<<M_ROWS / 32, 256, LNGEMM_SMEM>>>(
        ah, wot, bo, x, g1, be1, x1, x1h, D_MODEL);

    // ---- FFN1 (GELU) ----
    mma_gemm<1,1><<<dim3(16, M_ROWS / 128), 256, GEMM_SMEM>>>(
        x1h, w1t, b1, h16, 0, 0, D_MODEL, D_FF);

    // ---- FFN2 + residual + LN2 (fused, writes final output) ----
    ln_gemm<0><<<M_ROWS / 32, 256, LNGEMM_SMEM>>>(
        h16, w2t, b2, x1, g2, be2, out, nullptr, D_FF);
}

// round 16
// speedup vs baseline: 1.2848x; 1.2848x over previous
#include <cuda_runtime.h>
#include <cuda_fp16.h>
#include <math.h>

#define D_MODEL 512
#define N_HEADS 8
#define HEAD_E  64
#define D_FF    2048
#define BATCH   4
#define SEQ     2048
#define M_ROWS  (BATCH*SEQ)   /* 8192 */
#define LOG2E   1.4426950408889634f

// ---------------- scratch (device globals: allocation-guard safe) ----------
__device__ __half g_xh  [M_ROWS * D_MODEL];
__device__ __half g_qh  [M_ROWS * D_MODEL];
__device__ __half g_kh  [M_ROWS * D_MODEL];   // pre-scaled by log2e
__device__ __half g_vt  [BATCH * D_MODEL * SEQ];   // [b][col][l] transposed
__device__ __half g_ah  [M_ROWS * D_MODEL];
__device__ __half g_h16 [M_ROWS * D_FF];
__device__ __half g_x1h [M_ROWS * D_MODEL];
__device__ __half g_p16 [M_ROWS * D_MODEL];   // proj (fp16)
__device__ __half g_f16 [M_ROWS * D_MODEL];   // ffn2 out (fp16)
__device__ float  g_x1  [M_ROWS * D_MODEL];
__device__ __half g_wqkv[3 * D_MODEL * D_MODEL];   // [1536][512] transposed
__device__ __half g_wot [D_MODEL * D_MODEL];
__device__ __half g_w1t [D_FF * D_MODEL];
__device__ __half g_w2t [D_MODEL * D_FF];
__device__ float  g_bqkv[3 * D_MODEL];

// ---------------- helpers ----------------------------------------------------
__device__ __forceinline__ unsigned sptr(const void* p) {
    return (unsigned)__cvta_generic_to_shared(p);
}
__device__ __forceinline__ void cp16(const void* dst, const void* src) {
    asm volatile("cp.async.cg.shared.global [%0], [%1], 16;"
                 :: "r"(sptr(dst)), "l"(src));
}
#define CP_COMMIT() asm volatile("cp.async.commit_group;")
#define CP_WAIT0()  asm volatile("cp.async.wait_group 0;")
#define CP_WAIT1()  asm volatile("cp.async.wait_group 1;")

__device__ __forceinline__ unsigned pack_h2(float lo, float hi) {
    unsigned r;
    asm("cvt.rn.f16x2.f32 %0, %1, %2;" : "=r"(r) : "f"(hi), "f"(lo));
    return r;
}
__device__ __forceinline__ unsigned ex2_h2(unsigned a) {
    unsigned r;
    asm("ex2.approx.f16x2 %0, %1;" : "=r"(r) : "r"(a));
    return r;
}
__device__ __forceinline__ void mma16(float* c, const unsigned* a,
                                      unsigned b0, unsigned b1) {
    asm volatile(
        "mma.sync.aligned.m16n8k16.row.col.f32.f16.f16.f32 "
        "{%0,%1,%2,%3},{%4,%5,%6,%7},{%8,%9},{%0,%1,%2,%3};"
        : "+f"(c[0]), "+f"(c[1]), "+f"(c[2]), "+f"(c[3])
        : "r"(a[0]), "r"(a[1]), "r"(a[2]), "r"(a[3]), "r"(b0), "r"(b1));
}
__device__ __forceinline__ void ldsm4(unsigned* r, unsigned a) {
    asm volatile("ldmatrix.sync.aligned.m8n8.x4.shared.b16 {%0,%1,%2,%3}, [%4];"
                 : "=r"(r[0]), "=r"(r[1]), "=r"(r[2]), "=r"(r[3]) : "r"(a));
}
__device__ __forceinline__ float gelu_exact(float v) {
    return 0.5f * v * (1.0f + erff(v * 0.70710678118654752f));
}

// ---------------- merged prep kernel -----------------------------------------
__device__ __forceinline__ void do_transpose(const float* __restrict__ in,
                                             __half* __restrict__ out,
                                             int K, int N, int k0, int n0, int tid)
{
    __shared__ float tile[32][33];
    const int tx = tid & 31, ty = tid >> 5;
    #pragma unroll
    for (int i = 0; i < 32; i += 8)
        tile[ty + i][tx] = in[(size_t)(k0 + ty + i) * N + n0 + tx];
    __syncthreads();
    #pragma unroll
    for (int i = 0; i < 32; i += 8)
        out[(size_t)(n0 + ty + i) * K + k0 + tx] = __float2half(tile[tx][ty + i]);
}

__global__ void __launch_bounds__(256)
prep_kernel(const float* x, const float* Wq, const float* Wk, const float* Wv,
            const float* Wo, const float* W1, const float* W2,
            const float* bq, const float* bk, const float* bv,
            __half* xh, __half* wqkv, __half* wot, __half* w1t, __half* w2t,
            float* bqkv)
{
    const int blk = blockIdx.x;
    const int tid = threadIdx.x;
    if (blk < 1024) {
        const int z = blk >> 8, t = blk & 255;
        const float* in = (z == 0) ? Wq : (z == 1) ? Wk : (z == 2) ? Wv : Wo;
        __half* out = (z == 3) ? wot : (wqkv + (size_t)z * D_MODEL * D_MODEL);
        do_transpose(in, out, D_MODEL, D_MODEL, (t >> 4) * 32, (t & 15) * 32, tid);
    } else if (blk < 2048) {
        const int t = blk - 1024;
        do_transpose(W1, w1t, D_MODEL, D_FF, (t >> 6) * 32, (t & 63) * 32, tid);
    } else if (blk < 3072) {
        const int t = blk - 2048;
        do_transpose(W2, w2t, D_FF, D_MODEL, (t >> 4) * 32, (t & 15) * 32, tid);
    } else if (blk < 7168) {
        const int i = ((blk - 3072) * 256 + tid) * 4;
        float4 v = *(const float4*)&x[i];
        *(uint2*)&xh[i] = make_uint2(pack_h2(v.x, v.y), pack_h2(v.z, v.w));
    } else {
        const int i = (blk - 7168) * 256 + tid;
        if (i < D_MODEL) {
            bqkv[i] = bq[i];
            bqkv[D_MODEL + i] = bk[i];
            bqkv[2 * D_MODEL + i] = bv[i];
        }
    }
}

// ---------------- fp16 GEMM (mma.sync + ldmatrix, BK=32, 3-stage) ------------
// C[M,N] = A[M,K] @ Bt[N,K]^T + bias.
// OUT: 1 fp16 row-major, 3 QKV split epilogue (k scaled by log2e)
#define GS    20
#define GBUF  (128 * GS)
#define GEMM_SMEM (6 * GBUF * 4)

template<int ACT, int OUT>
__global__ void __launch_bounds__(256, 2)
mma_gemm(const __half* __restrict__ A, const __half* __restrict__ Bt,
         const float* __restrict__ bias, void* Cv, void* Cv2, void* Cv3,
         int K, int N)
{
    extern __shared__ unsigned smu[];
    const unsigned sb = sptr(smu);

    const int tid  = threadIdx.x;
    const int warp = tid >> 5, lane = tid & 31;
    const int wm   = warp >> 1, wn = warp & 1;
    const int lr   = lane >> 2, lc = lane & 3;
    const int m8   = lane >> 3, j8 = lane & 7;
    const int m0   = blockIdx.y * 128;
    const int n0   = blockIdx.x * 128;

    const int row = tid >> 1;
    const int hf  = tid & 1;

    unsigned aoff[2], boff[4];
    #pragma unroll
    for (int tm = 0; tm < 2; tm++)
        aoff[tm] = (unsigned)((wm * 32 + tm * 16 + (m8 & 1) * 8 + j8) * (GS * 4)
                              + (m8 >> 1) * 16);
    #pragma unroll
    for (int tnp = 0; tnp < 4; tnp++)
        boff[tnp] = (unsigned)((wn * 64 + tnp * 16 + (m8 >> 1) * 8 + j8) * (GS * 4)
                               + (m8 & 1) * 16);

    float acc[2][8][4];
    #pragma unroll
    for (int i = 0; i < 2; i++)
        #pragma unroll
        for (int j = 0; j < 8; j++)
            #pragma unroll
            for (int r = 0; r < 4; r++) acc[i][j][r] = 0.0f;

    const int KT = K >> 5;

    auto issue = [&](int kt, int buf) {
        const __half* sa = A  + (size_t)(m0 + row) * K + (kt << 5) + (hf << 4);
        unsigned* da = smu + buf * GBUF + row * GS + (hf << 3);
        cp16(da,     sa);
        cp16(da + 4, sa + 8);
        const __half* sbp = Bt + (size_t)(n0 + row) * K + (kt << 5) + (hf << 4);
        unsigned* db = smu + (3 + buf) * GBUF + row * GS + (hf << 3);
        cp16(db,     sbp);
        cp16(db + 4, sbp + 8);
    };

    issue(0, 0);
    CP_COMMIT();
    if (KT > 1) { issue(1, 1); CP_COMMIT(); }

    int bufc = 0;
    for (int kt = 0; kt < KT; kt++) {
        if (kt + 1 < KT) CP_WAIT1(); else CP_WAIT0();
        __syncthreads();
        if (kt + 2 < KT) {
            int nb = bufc + 2; if (nb >= 3) nb -= 3;
            issue(kt + 2, nb);
            CP_COMMIT();
        }

        const unsigned aB = sb + bufc * (GBUF * 4);
        const unsigned bB = sb + (3 + bufc) * (GBUF * 4);

        #pragma unroll
        for (int ks = 0; ks < 2; ks++) {
            unsigned af[2][4];
            ldsm4(af[0], aB + aoff[0] + ks * 32);
            ldsm4(af[1], aB + aoff[1] + ks * 32);
            #pragma unroll
            for (int tnp = 0; tnp < 4; tnp++) {
                unsigned bf[4];
                ldsm4(bf, bB + boff[tnp] + ks * 32);
                mma16(acc[0][2 * tnp],     af[0], bf[0], bf[1]);
                mma16(acc[1][2 * tnp],     af[1], bf[0], bf[1]);
                mma16(acc[0][2 * tnp + 1], af[0], bf[2], bf[3]);
                mma16(acc[1][2 * tnp + 1], af[1], bf[2], bf[3]);
            }
        }
        bufc = (bufc == 2) ? 0 : bufc + 1;
    }

    // epilogue
    #pragma unroll
    for (int tm = 0; tm < 2; tm++) {
        #pragma unroll
        for (int tn = 0; tn < 8; tn++) {
            const int rw  = m0 + wm * 32 + tm * 16 + lr;
            const int col = n0 + wn * 64 + tn * 8 + 2 * lc;
            const float b0 = bias[col], b1 = bias[col + 1];
            float2 v0 = make_float2(acc[tm][tn][0] + b0, acc[tm][tn][1] + b1);
            float2 v1 = make_float2(acc[tm][tn][2] + b0, acc[tm][tn][3] + b1);
            if (ACT) {
                v0.x = gelu_exact(v0.x); v0.y = gelu_exact(v0.y);
                v1.x = gelu_exact(v1.x); v1.y = gelu_exact(v1.y);
            }
            if (OUT == 1) {
                __half* C = (__half*)Cv;
                *(unsigned*)&C[(size_t)rw * N + col]       = pack_h2(v0.x, v0.y);
                *(unsigned*)&C[(size_t)(rw + 8) * N + col] = pack_h2(v1.x, v1.y);
            } else {
                if (col < 1024) {
                    __half* C = (__half*)(col < 512 ? Cv : Cv2);
                    if (col >= 512) {   // k segment: fold log2e into k
                        v0.x *= LOG2E; v0.y *= LOG2E;
                        v1.x *= LOG2E; v1.y *= LOG2E;
                    }
                    const int c = col & 511;
                    *(unsigned*)&C[(size_t)rw * D_MODEL + c]       = pack_h2(v0.x, v0.y);
                    *(unsigned*)&C[(size_t)(rw + 8) * D_MODEL + c] = pack_h2(v1.x, v1.y);
                } else {
                    __half* C = (__half*)Cv3;
                    const int c  = col - 1024;
                    const int bb = rw >> 11, ll = rw & 2047;
                    C[((size_t)(bb * D_MODEL + c))     * SEQ + ll]     = __float2half(v0.x);
                    C[((size_t)(bb * D_MODEL + c + 1)) * SEQ + ll]     = __float2half(v0.y);
                    C[((size_t)(bb * D_MODEL + c))     * SEQ + ll + 8] = __float2half(v1.x);
                    C[((size_t)(bb * D_MODEL + c + 1)) * SEQ + ll + 8] = __float2half(v1.y);
                }
            }
        }
    }
}

// ---------------- fused flash attention (h2 exp softmax) ---------------------
// K pre-scaled by log2e, Q scaled by 1/8 -> S is in log2 domain.
#define FKV_STRIDE 36
#define FKV_BUF    (64 * FKV_STRIDE)
#define FLASH_SMEM (6 * FKV_BUF * 4)

__global__ void __launch_bounds__(256, 2)
flash_kernel(const __half* __restrict__ Qh, const __half* __restrict__ Kh,
             const __half* __restrict__ Vt, __half* __restrict__ Oh)
{
    extern __shared__ unsigned smu[];
    const unsigned sb = sptr(smu);

    const int tid  = threadIdx.x;
    const int warp = tid >> 5, lane = tid & 31;
    const int lr   = lane >> 2, lc = lane & 3;
    const int m8   = lane >> 3, j8 = lane & 7;
    const int bh   = blockIdx.y;
    const int b    = bh >> 3, h = bh & 7;
    const int ql0  = blockIdx.x * 128;

    const __half* Qb = Qh + ((size_t)(b * SEQ + ql0)) * D_MODEL + h * HEAD_E;
    const __half* Kb = Kh + ((size_t)(b * SEQ)) * D_MODEL + h * HEAD_E;
    const __half* Vb = Vt + ((size_t)(b * D_MODEL + h * HEAD_E)) * SEQ;

    unsigned qf[4][4];
    {
        const __half2 s8 = __half2half2(__float2half(0.125f));
        const __half* q0 = Qb + (size_t)(warp * 16 + lr) * D_MODEL;
        const __half* q1 = q0 + 8 * D_MODEL;
        #pragma unroll
        for (int ks = 0; ks < 4; ks++) {
            const int e0 = ks * 16 + 2 * lc;
            __half2 t;
            t = __hmul2(*(const __half2*)(q0 + e0), s8);     qf[ks][0] = *(unsigned*)&t;
            t = __hmul2(*(const __half2*)(q1 + e0), s8);     qf[ks][1] = *(unsigned*)&t;
            t = __hmul2(*(const __half2*)(q0 + e0 + 8), s8); qf[ks][2] = *(unsigned*)&t;
            t = __hmul2(*(const __half2*)(q1 + e0 + 8), s8); qf[ks][3] = *(unsigned*)&t;
        }
    }

    unsigned kvoff[4];
    #pragma unroll
    for (int tnp = 0; tnp < 4; tnp++)
        kvoff[tnp] = (unsigned)((tnp * 16 + (m8 >> 1) * 8 + j8) * (FKV_STRIDE * 4)
                                + (m8 & 1) * 16);

    const int lrow = tid >> 2;
    const int lch  = (tid & 3) << 1;
    auto issue = [&](int t, int buf) {
        const int s0 = t << 6;
        unsigned* Kd = smu + buf * FKV_BUF + lrow * FKV_STRIDE + lch * 4;
        const __half* ksrc = Kb + (size_t)(s0 + lrow) * D_MODEL + lch * 8;
        cp16(Kd,     ksrc);
        cp16(Kd + 4, ksrc + 8);
        unsigned* Vd = smu + (3 + buf) * FKV_BUF + lrow * FKV_STRIDE + lch * 4;
        const __half* vsrc = Vb + (size_t)lrow * SEQ + s0 + lch * 8;
        cp16(Vd,     vsrc);
        cp16(Vd + 4, vsrc + 8);
    };

    float oacc[8][4];
    #pragma unroll
    for (int t = 0; t < 8; t++)
        #pragma unroll
        for (int r = 0; r < 4; r++) oacc[t][r] = 0.0f;
    float ls0 = 0.0f, ls1 = 0.0f;

    const int NT = SEQ / 64;
    issue(0, 0);
    CP_COMMIT();
    issue(1, 1);
    CP_COMMIT();

    int bufc = 0;
    for (int t = 0; t < NT; t++) {
        if (t + 1 < NT) CP_WAIT1(); else CP_WAIT0();
        __syncthreads();
        if (t + 2 < NT) {
            int nb = bufc + 2; if (nb >= 3) nb -= 3;
            issue(t + 2, nb);
            CP_COMMIT();
        }

        const unsigned kB = sb + bufc * (FKV_BUF * 4);
        const unsigned vB = sb + (3 + bufc) * (FKV_BUF * 4);

        float sacc[8][4];
        #pragma unroll
        for (int tn = 0; tn < 8; tn++)
            #pragma unroll
            for (int r = 0; r < 4; r++) sacc[tn][r] = 0.0f;
        #pragma unroll
        for (int ks = 0; ks < 4; ks++) {
            #pragma unroll
            for (int tnp = 0; tnp < 4; tnp++) {
                unsigned bf[4];
                ldsm4(bf, kB + kvoff[tnp] + ks * 32);
                mma16(sacc[2 * tnp],     qf[ks], bf[0], bf[1]);
                mma16(sacc[2 * tnp + 1], qf[ks], bf[2], bf[3]);
            }
        }

        unsigned pk0[8], pk1[8];
        #pragma unroll
        for (int tn = 0; tn < 8; tn++) {
            pk0[tn] = ex2_h2(pack_h2(sacc[tn][0], sacc[tn][1]));
            pk1[tn] = ex2_h2(pack_h2(sacc[tn][2], sacc[tn][3]));
        }
        __half2 a0 = __half2half2(__float2half(0.0f));
        __half2 a1 = a0;
        #pragma unroll
        for (int tn = 0; tn < 8; tn++) {
            a0 = __hadd2(a0, *(const __half2*)&pk0[tn]);
            a1 = __hadd2(a1, *(const __half2*)&pk1[tn]);
        }
        float2 f0 = __half22float2(a0);
        float2 f1 = __half22float2(a1);
        float ps0 = f0.x + f0.y;
        float ps1 = f1.x + f1.y;
        ps0 += __shfl_xor_sync(0xFFFFFFFFu, ps0, 1);
        ps0 += __shfl_xor_sync(0xFFFFFFFFu, ps0, 2);
        ps1 += __shfl_xor_sync(0xFFFFFFFFu, ps1, 1);
        ps1 += __shfl_xor_sync(0xFFFFFFFFu, ps1, 2);
        ls0 += ps0;
        ls1 += ps1;

        #pragma unroll
        for (int ks = 0; ks < 4; ks++) {
            unsigned af[4];
            af[0] = pk0[2 * ks];
            af[1] = pk1[2 * ks];
            af[2] = pk0[2 * ks + 1];
            af[3] = pk1[2 * ks + 1];
            #pragma unroll
            for (int tnp = 0; tnp < 4; tnp++) {
                unsigned bf[4];
                ldsm4(bf, vB + kvoff[tnp] + ks * 32);
                mma16(oacc[2 * tnp],     af, bf[0], bf[1]);
                mma16(oacc[2 * tnp + 1], af, bf[2], bf[3]);
            }
        }
        bufc = (bufc == 2) ? 0 : bufc + 1;
    }

    const float inv0 = 1.0f / ls0, inv1 = 1.0f / ls1;
    __half* O0 = Oh + ((size_t)(b * SEQ + ql0 + warp * 16 + lr)) * D_MODEL + h * HEAD_E;
    __half* O1 = O0 + 8 * D_MODEL;
    #pragma unroll
    for (int tn = 0; tn < 8; tn++) {
        const int col = tn * 8 + 2 * lc;
        *(unsigned*)&O0[col] = pack_h2(oacc[tn][0] * inv0, oacc[tn][1] * inv0);
        *(unsigned*)&O1[col] = pack_h2(oacc[tn][2] * inv1, oacc[tn][3] * inv1);
    }
}

// ---------------- residual add + LayerNorm (Y fp16) --------------------------
template<int WRITE16>
__global__ void __launch_bounds__(128)
add_ln_kernel(const float* __restrict__ X, const __half* __restrict__ Y,
              const float* __restrict__ g, const float* __restrict__ bta,
              float* __restrict__ Out, __half* __restrict__ Out16)
{
    __shared__ float red[8];
    const int row = blockIdx.x;
    const int tid = threadIdx.x;
    const int col = tid * 4;

    float4 xv = *(const float4*)&X[(size_t)row * D_MODEL + col];
    uint2  yu = *(const uint2*)&Y[(size_t)row * D_MODEL + col];
    float2 ya = __half22float2(*(const __half2*)&yu.x);
    float2 yb = __half22float2(*(const __half2*)&yu.y);
    float v0 = xv.x + ya.x, v1 = xv.y + ya.y, v2 = xv.z + yb.x, v3 = xv.w + yb.y;

    float sum = v0 + v1 + v2 + v3;
    float sq  = v0 * v0 + v1 * v1 + v2 * v2 + v3 * v3;
    #pragma unroll
    for (int off = 16; off > 0; off >>= 1) {
        sum += __shfl_xor_sync(0xFFFFFFFFu, sum, off);
        sq  += __shfl_xor_sync(0xFFFFFFFFu, sq,  off);
    }
    const int wid  = tid >> 5;
    const int lane = tid & 31;
    if (lane == 0) { red[wid] = sum; red[4 + wid] = sq; }
    __syncthreads();
    sum = red[0] + red[1] + red[2] + red[3];
    sq  = red[4] + red[5] + red[6] + red[7];

    const float mu  = sum * (1.0f / D_MODEL);
    const float var = sq * (1.0f / D_MODEL) - mu * mu;
    const float rst = rsqrtf(var + 1e-5f);

    float4 gv = *(const float4*)&g[col];
    float4 bv = *(const float4*)&bta[col];
    float4 w;
    w.x = (v0 - mu) * rst * gv.x + bv.x;
    w.y = (v1 - mu) * rst * gv.y + bv.y;
    w.z = (v2 - mu) * rst * gv.z + bv.z;
    w.w = (v3 - mu) * rst * gv.w + bv.w;
    *(float4*)&Out[(size_t)row * D_MODEL + col] = w;
    if (WRITE16)
        *(uint2*)&Out16[(size_t)row * D_MODEL + col] =
            make_uint2(pack_h2(w.x, w.y), pack_h2(w.z, w.w));
}

// ---------------- launcher --------------------------------------------------
extern "C" void kernel_launch(void* const* d_in, const int* in_sizes, int n_in,
                              void* d_out, int out_size)
{
    const float* x   = (const float*)d_in[0];
    const float* Wq  = (const float*)d_in[1];
    const float* bq  = (const float*)d_in[2];
    const float* Wk  = (const float*)d_in[3];
    const float* bk  = (const float*)d_in[4];
    const float* Wv  = (const float*)d_in[5];
    const float* bv  = (const float*)d_in[6];
    const float* Wo  = (const float*)d_in[7];
    const float* bo  = (const float*)d_in[8];
    const float* W1  = (const float*)d_in[9];
    const float* b1  = (const float*)d_in[10];
    const float* W2  = (const float*)d_in[11];
    const float* b2  = (const float*)d_in[12];
    const float* g1  = (const float*)d_in[13];
    const float* be1 = (const float*)d_in[14];
    const float* g2  = (const float*)d_in[15];
    const float* be2 = (const float*)d_in[16];
    float* out = (float*)d_out;

    __half *xh, *qh, *kh, *vt, *ah, *h16, *x1h, *p16, *f16, *wqkv, *wot, *w1t, *w2t;
    float *x1, *bqkv;
    cudaGetSymbolAddress((void**)&xh,   g_xh);
    cudaGetSymbolAddress((void**)&qh,   g_qh);
    cudaGetSymbolAddress((void**)&kh,   g_kh);
    cudaGetSymbolAddress((void**)&vt,   g_vt);
    cudaGetSymbolAddress((void**)&ah,   g_ah);
    cudaGetSymbolAddress((void**)&h16,  g_h16);
    cudaGetSymbolAddress((void**)&x1h,  g_x1h);
    cudaGetSymbolAddress((void**)&p16,  g_p16);
    cudaGetSymbolAddress((void**)&f16,  g_f16);
    cudaGetSymbolAddress((void**)&wqkv, g_wqkv);
    cudaGetSymbolAddress((void**)&wot,  g_wot);
    cudaGetSymbolAddress((void**)&w1t,  g_w1t);
    cudaGetSymbolAddress((void**)&w2t,  g_w2t);
    cudaGetSymbolAddress((void**)&x1,   g_x1);
    cudaGetSymbolAddress((void**)&bqkv, g_bqkv);

    cudaFuncSetAttribute((const void*)mma_gemm<0,1>,
                         cudaFuncAttributeMaxDynamicSharedMemorySize, GEMM_SMEM);
    cudaFuncSetAttribute((const void*)mma_gemm<0,3>,
                         cudaFuncAttributeMaxDynamicSharedMemorySize, GEMM_SMEM);
    cudaFuncSetAttribute((const void*)mma_gemm<1,1>,
                         cudaFuncAttributeMaxDynamicSharedMemorySize, GEMM_SMEM);
    cudaFuncSetAttribute((const void*)flash_kernel,
                         cudaFuncAttributeMaxDynamicSharedMemorySize, FLASH_SMEM);

    // ---- prep (single merged launch) ----
    prep_kernel<<<7170, 256>>>(x, Wq, Wk, Wv, Wo, W1, W2, bq, bk, bv,
                               xh, wqkv, wot, w1t, w2t, bqkv);

    // ---- fused QKV projection (k pre-scaled by log2e in epilogue) ----
    mma_gemm<0,3><<<dim3(12, M_ROWS / 128), 256, GEMM_SMEM>>>(
        xh, wqkv, bqkv, qh, kh, vt, D_MODEL, 3 * D_MODEL);

    // ---- flash attention ----
    flash_kernel<<<dim3(SEQ / 128, BATCH * N_HEADS), 256, FLASH_SMEM>>>(qh, kh, vt, ah);

    // ---- output projection (fp16 out) + residual LN1 ----
    mma_gemm<0,1><<<dim3(4, M_ROWS / 128), 256, GEMM_SMEM>>>(
        ah, wot, bo, p16, 0, 0, D_MODEL, D_MODEL);
    add_ln_kernel<1><<<M_ROWS, 128>>>(x, p16, g1, be1, x1, x1h);

    // ---- FFN + residual LN2 ----
    mma_gemm<1,1><<<dim3(16, M_ROWS / 128), 256, GEMM_SMEM>>>(
        x1h, w1t, b1, h16, 0, 0, D_MODEL, D_FF);
    mma_gemm<0,1><<<dim3(4, M_ROWS / 128), 256, GEMM_SMEM>>>(
        h16, w2t, b2, f16, 0, 0, D_FF, D_MODEL);
    add_ln_kernel<0><<<M_ROWS, 128>>>(x1, f16, g2, be2, out, nullptr);
}

// round 17
// speedup vs baseline: 1.2903x; 1.0043x over previous
#include <cuda_runtime.h>
#include <cuda_fp16.h>
#include <math.h>

#define D_MODEL 512
#define N_HEADS 8
#define HEAD_E  64
#define D_FF    2048
#define BATCH   4
#define SEQ     2048
#define M_ROWS  (BATCH*SEQ)   /* 8192 */
#define LOG2E   1.4426950408889634f

// ---------------- scratch (device globals: allocation-guard safe) ----------
__device__ __half g_xh  [M_ROWS * D_MODEL];
__device__ __half g_qh  [M_ROWS * D_MODEL];
__device__ __half g_kh  [M_ROWS * D_MODEL];   // pre-scaled by log2e
__device__ __half g_vt  [BATCH * D_MODEL * SEQ];   // [b][col][l] transposed
__device__ __half g_ah  [M_ROWS * D_MODEL];
__device__ __half g_h16 [M_ROWS * D_FF];
__device__ __half g_x1h [M_ROWS * D_MODEL];   // LN1 out (fp16, residual + FFN in)
__device__ __half g_p16 [M_ROWS * D_MODEL];   // proj (fp16)
__device__ __half g_f16 [M_ROWS * D_MODEL];   // ffn2 out (fp16)
__device__ __half g_wqkv[3 * D_MODEL * D_MODEL];   // [1536][512] transposed
__device__ __half g_wot [D_MODEL * D_MODEL];
__device__ __half g_w1t [D_FF * D_MODEL];
__device__ __half g_w2t [D_MODEL * D_FF];
__device__ float  g_bqkv[3 * D_MODEL];

// ---------------- helpers ----------------------------------------------------
__device__ __forceinline__ unsigned sptr(const void* p) {
    return (unsigned)__cvta_generic_to_shared(p);
}
__device__ __forceinline__ void cp16(const void* dst, const void* src) {
    asm volatile("cp.async.cg.shared.global [%0], [%1], 16;"
                 :: "r"(sptr(dst)), "l"(src));
}
#define CP_COMMIT() asm volatile("cp.async.commit_group;")
#define CP_WAIT0()  asm volatile("cp.async.wait_group 0;")
#define CP_WAIT1()  asm volatile("cp.async.wait_group 1;")

__device__ __forceinline__ unsigned pack_h2(float lo, float hi) {
    unsigned r;
    asm("cvt.rn.f16x2.f32 %0, %1, %2;" : "=r"(r) : "f"(hi), "f"(lo));
    return r;
}
__device__ __forceinline__ unsigned ex2_h2(unsigned a) {
    unsigned r;
    asm("ex2.approx.f16x2 %0, %1;" : "=r"(r) : "r"(a));
    return r;
}
__device__ __forceinline__ void mma16(float* c, const unsigned* a,
                                      unsigned b0, unsigned b1) {
    asm volatile(
        "mma.sync.aligned.m16n8k16.row.col.f32.f16.f16.f32 "
        "{%0,%1,%2,%3},{%4,%5,%6,%7},{%8,%9},{%0,%1,%2,%3};"
        : "+f"(c[0]), "+f"(c[1]), "+f"(c[2]), "+f"(c[3])
        : "r"(a[0]), "r"(a[1]), "r"(a[2]), "r"(a[3]), "r"(b0), "r"(b1));
}
__device__ __forceinline__ void ldsm4(unsigned* r, unsigned a) {
    asm volatile("ldmatrix.sync.aligned.m8n8.x4.shared.b16 {%0,%1,%2,%3}, [%4];"
                 : "=r"(r[0]), "=r"(r[1]), "=r"(r[2]), "=r"(r[3]) : "r"(a));
}
__device__ __forceinline__ float gelu_exact(float v) {
    return 0.5f * v * (1.0f + erff(v * 0.70710678118654752f));
}

// ---------------- merged prep kernel -----------------------------------------
__device__ __forceinline__ void do_transpose(const float* __restrict__ in,
                                             __half* __restrict__ out,
                                             int K, int N, int k0, int n0, int tid)
{
    __shared__ float tile[32][33];
    const int tx = tid & 31, ty = tid >> 5;
    #pragma unroll
    for (int i = 0; i < 32; i += 8)
        tile[ty + i][tx] = in[(size_t)(k0 + ty + i) * N + n0 + tx];
    __syncthreads();
    #pragma unroll
    for (int i = 0; i < 32; i += 8)
        out[(size_t)(n0 + ty + i) * K + k0 + tx] = __float2half(tile[tx][ty + i]);
}

__global__ void __launch_bounds__(256)
prep_kernel(const float* x, const float* Wq, const float* Wk, const float* Wv,
            const float* Wo, const float* W1, const float* W2,
            const float* bq, const float* bk, const float* bv,
            __half* xh, __half* wqkv, __half* wot, __half* w1t, __half* w2t,
            float* bqkv)
{
    const int blk = blockIdx.x;
    const int tid = threadIdx.x;
    if (blk < 1024) {
        const int z = blk >> 8, t = blk & 255;
        const float* in = (z == 0) ? Wq : (z == 1) ? Wk : (z == 2) ? Wv : Wo;
        __half* out = (z == 3) ? wot : (wqkv + (size_t)z * D_MODEL * D_MODEL);
        do_transpose(in, out, D_MODEL, D_MODEL, (t >> 4) * 32, (t & 15) * 32, tid);
    } else if (blk < 2048) {
        const int t = blk - 1024;
        do_transpose(W1, w1t, D_MODEL, D_FF, (t >> 6) * 32, (t & 63) * 32, tid);
    } else if (blk < 3072) {
        const int t = blk - 2048;
        do_transpose(W2, w2t, D_FF, D_MODEL, (t >> 4) * 32, (t & 15) * 32, tid);
    } else if (blk < 7168) {
        const int i = ((blk - 3072) * 256 + tid) * 4;
        float4 v = *(const float4*)&x[i];
        *(uint2*)&xh[i] = make_uint2(pack_h2(v.x, v.y), pack_h2(v.z, v.w));
    } else {
        const int i = (blk - 7168) * 256 + tid;
        if (i < D_MODEL) {
            bqkv[i] = bq[i];
            bqkv[D_MODEL + i] = bk[i];
            bqkv[2 * D_MODEL + i] = bv[i];
        }
    }
}

// ---------------- fp16 GEMM (mma.sync + ldmatrix, BK=32, 3-stage) ------------
// C[M,N] = A[M,K] @ Bt[N,K]^T + bias.
// OUT: 1 fp16 row-major, 3 QKV split epilogue (k scaled by log2e)
#define GS    20
#define GBUF  (128 * GS)
#define GEMM_SMEM (6 * GBUF * 4)

template<int ACT, int OUT>
__global__ void __launch_bounds__(256, 2)
mma_gemm(const __half* __restrict__ A, const __half* __restrict__ Bt,
         const float* __restrict__ bias, void* Cv, void* Cv2, void* Cv3,
         int K, int N)
{
    extern __shared__ unsigned smu[];
    const unsigned sb = sptr(smu);

    const int tid  = threadIdx.x;
    const int warp = tid >> 5, lane = tid & 31;
    const int wm   = warp >> 1, wn = warp & 1;
    const int lr   = lane >> 2, lc = lane & 3;
    const int m8   = lane >> 3, j8 = lane & 7;
    const int m0   = blockIdx.y * 128;
    const int n0   = blockIdx.x * 128;

    const int row = tid >> 1;
    const int hf  = tid & 1;

    unsigned aoff[2], boff[4];
    #pragma unroll
    for (int tm = 0; tm < 2; tm++)
        aoff[tm] = (unsigned)((wm * 32 + tm * 16 + (m8 & 1) * 8 + j8) * (GS * 4)
                              + (m8 >> 1) * 16);
    #pragma unroll
    for (int tnp = 0; tnp < 4; tnp++)
        boff[tnp] = (unsigned)((wn * 64 + tnp * 16 + (m8 >> 1) * 8 + j8) * (GS * 4)
                               + (m8 & 1) * 16);

    float acc[2][8][4];
    #pragma unroll
    for (int i = 0; i < 2; i++)
        #pragma unroll
        for (int j = 0; j < 8; j++)
            #pragma unroll
            for (int r = 0; r < 4; r++) acc[i][j][r] = 0.0f;

    const int KT = K >> 5;

    auto issue = [&](int kt, int buf) {
        const __half* sa = A  + (size_t)(m0 + row) * K + (kt << 5) + (hf << 4);
        unsigned* da = smu + buf * GBUF + row * GS + (hf << 3);
        cp16(da,     sa);
        cp16(da + 4, sa + 8);
        const __half* sbp = Bt + (size_t)(n0 + row) * K + (kt << 5) + (hf << 4);
        unsigned* db = smu + (3 + buf) * GBUF + row * GS + (hf << 3);
        cp16(db,     sbp);
        cp16(db + 4, sbp + 8);
    };

    issue(0, 0);
    CP_COMMIT();
    if (KT > 1) { issue(1, 1); CP_COMMIT(); }

    int bufc = 0;
    for (int kt = 0; kt < KT; kt++) {
        if (kt + 1 < KT) CP_WAIT1(); else CP_WAIT0();
        __syncthreads();
        if (kt + 2 < KT) {
            int nb = bufc + 2; if (nb >= 3) nb -= 3;
            issue(kt + 2, nb);
            CP_COMMIT();
        }

        const unsigned aB = sb + bufc * (GBUF * 4);
        const unsigned bB = sb + (3 + bufc) * (GBUF * 4);

        #pragma unroll
        for (int ks = 0; ks < 2; ks++) {
            unsigned af[2][4];
            ldsm4(af[0], aB + aoff[0] + ks * 32);
            ldsm4(af[1], aB + aoff[1] + ks * 32);
            #pragma unroll
            for (int tnp = 0; tnp < 4; tnp++) {
                unsigned bf[4];
                ldsm4(bf, bB + boff[tnp] + ks * 32);
                mma16(acc[0][2 * tnp],     af[0], bf[0], bf[1]);
                mma16(acc[1][2 * tnp],     af[1], bf[0], bf[1]);
                mma16(acc[0][2 * tnp + 1], af[0], bf[2], bf[3]);
                mma16(acc[1][2 * tnp + 1], af[1], bf[2], bf[3]);
            }
        }
        bufc = (bufc == 2) ? 0 : bufc + 1;
    }

    // epilogue
    #pragma unroll
    for (int tm = 0; tm < 2; tm++) {
        #pragma unroll
        for (int tn = 0; tn < 8; tn++) {
            const int rw  = m0 + wm * 32 + tm * 16 + lr;
            const int col = n0 + wn * 64 + tn * 8 + 2 * lc;
            const float b0 = bias[col], b1 = bias[col + 1];
            float2 v0 = make_float2(acc[tm][tn][0] + b0, acc[tm][tn][1] + b1);
            float2 v1 = make_float2(acc[tm][tn][2] + b0, acc[tm][tn][3] + b1);
            if (ACT) {
                v0.x = gelu_exact(v0.x); v0.y = gelu_exact(v0.y);
                v1.x = gelu_exact(v1.x); v1.y = gelu_exact(v1.y);
            }
            if (OUT == 1) {
                __half* C = (__half*)Cv;
                *(unsigned*)&C[(size_t)rw * N + col]       = pack_h2(v0.x, v0.y);
                *(unsigned*)&C[(size_t)(rw + 8) * N + col] = pack_h2(v1.x, v1.y);
            } else {
                if (col < 1024) {
                    __half* C = (__half*)(col < 512 ? Cv : Cv2);
                    if (col >= 512) {   // k segment: fold log2e into k
                        v0.x *= LOG2E; v0.y *= LOG2E;
                        v1.x *= LOG2E; v1.y *= LOG2E;
                    }
                    const int c = col & 511;
                    *(unsigned*)&C[(size_t)rw * D_MODEL + c]       = pack_h2(v0.x, v0.y);
                    *(unsigned*)&C[(size_t)(rw + 8) * D_MODEL + c] = pack_h2(v1.x, v1.y);
                } else {
                    __half* C = (__half*)Cv3;
                    const int c  = col - 1024;
                    const int bb = rw >> 11, ll = rw & 2047;
                    C[((size_t)(bb * D_MODEL + c))     * SEQ + ll]     = __float2half(v0.x);
                    C[((size_t)(bb * D_MODEL + c + 1)) * SEQ + ll]     = __float2half(v0.y);
                    C[((size_t)(bb * D_MODEL + c))     * SEQ + ll + 8] = __float2half(v1.x);
                    C[((size_t)(bb * D_MODEL + c + 1)) * SEQ + ll + 8] = __float2half(v1.y);
                }
            }
        }
    }
}

// ---------------- fused flash attention (h2 exp softmax) ---------------------
// K pre-scaled by log2e, Q scaled by 1/8 -> S is in log2 domain.
#define FKV_STRIDE 36
#define FKV_BUF    (64 * FKV_STRIDE)
#define FLASH_SMEM (6 * FKV_BUF * 4)

__global__ void __launch_bounds__(256, 2)
flash_kernel(const __half* __restrict__ Qh, const __half* __restrict__ Kh,
             const __half* __restrict__ Vt, __half* __restrict__ Oh)
{
    extern __shared__ unsigned smu[];
    const unsigned sb = sptr(smu);

    const int tid  = threadIdx.x;
    const int warp = tid >> 5, lane = tid & 31;
    const int lr   = lane >> 2, lc = lane & 3;
    const int m8   = lane >> 3, j8 = lane & 7;
    const int bh   = blockIdx.y;
    const int b    = bh >> 3, h = bh & 7;
    const int ql0  = blockIdx.x * 128;

    const __half* Qb = Qh + ((size_t)(b * SEQ + ql0)) * D_MODEL + h * HEAD_E;
    const __half* Kb = Kh + ((size_t)(b * SEQ)) * D_MODEL + h * HEAD_E;
    const __half* Vb = Vt + ((size_t)(b * D_MODEL + h * HEAD_E)) * SEQ;

    unsigned qf[4][4];
    {
        const __half2 s8 = __half2half2(__float2half(0.125f));
        const __half* q0 = Qb + (size_t)(warp * 16 + lr) * D_MODEL;
        const __half* q1 = q0 + 8 * D_MODEL;
        #pragma unroll
        for (int ks = 0; ks < 4; ks++) {
            const int e0 = ks * 16 + 2 * lc;
            __half2 t;
            t = __hmul2(*(const __half2*)(q0 + e0), s8);     qf[ks][0] = *(unsigned*)&t;
            t = __hmul2(*(const __half2*)(q1 + e0), s8);     qf[ks][1] = *(unsigned*)&t;
            t = __hmul2(*(const __half2*)(q0 + e0 + 8), s8); qf[ks][2] = *(unsigned*)&t;
            t = __hmul2(*(const __half2*)(q1 + e0 + 8), s8); qf[ks][3] = *(unsigned*)&t;
        }
    }

    unsigned kvoff[4];
    #pragma unroll
    for (int tnp = 0; tnp < 4; tnp++)
        kvoff[tnp] = (unsigned)((tnp * 16 + (m8 >> 1) * 8 + j8) * (FKV_STRIDE * 4)
                                + (m8 & 1) * 16);

    const int lrow = tid >> 2;
    const int lch  = (tid & 3) << 1;
    auto issue = [&](int t, int buf) {
        const int s0 = t << 6;
        unsigned* Kd = smu + buf * FKV_BUF + lrow * FKV_STRIDE + lch * 4;
        const __half* ksrc = Kb + (size_t)(s0 + lrow) * D_MODEL + lch * 8;
        cp16(Kd,     ksrc);
        cp16(Kd + 4, ksrc + 8);
        unsigned* Vd = smu + (3 + buf) * FKV_BUF + lrow * FKV_STRIDE + lch * 4;
        const __half* vsrc = Vb + (size_t)lrow * SEQ + s0 + lch * 8;
        cp16(Vd,     vsrc);
        cp16(Vd + 4, vsrc + 8);
    };

    float oacc[8][4];
    #pragma unroll
    for (int t = 0; t < 8; t++)
        #pragma unroll
        for (int r = 0; r < 4; r++) oacc[t][r] = 0.0f;
    float ls0 = 0.0f, ls1 = 0.0f;

    const int NT = SEQ / 64;
    issue(0, 0);
    CP_COMMIT();
    issue(1, 1);
    CP_COMMIT();

    int bufc = 0;
    for (int t = 0; t < NT; t++) {
        if (t + 1 < NT) CP_WAIT1(); else CP_WAIT0();
        __syncthreads();
        if (t + 2 < NT) {
            int nb = bufc + 2; if (nb >= 3) nb -= 3;
            issue(t + 2, nb);
            CP_COMMIT();
        }

        const unsigned kB = sb + bufc * (FKV_BUF * 4);
        const unsigned vB = sb + (3 + bufc) * (FKV_BUF * 4);

        float sacc[8][4];
        #pragma unroll
        for (int tn = 0; tn < 8; tn++)
            #pragma unroll
            for (int r = 0; r < 4; r++) sacc[tn][r] = 0.0f;
        #pragma unroll
        for (int ks = 0; ks < 4; ks++) {
            #pragma unroll
            for (int tnp = 0; tnp < 4; tnp++) {
                unsigned bf[4];
                ldsm4(bf, kB + kvoff[tnp] + ks * 32);
                mma16(sacc[2 * tnp],     qf[ks], bf[0], bf[1]);
                mma16(sacc[2 * tnp + 1], qf[ks], bf[2], bf[3]);
            }
        }

        unsigned pk0[8], pk1[8];
        #pragma unroll
        for (int tn = 0; tn < 8; tn++) {
            pk0[tn] = ex2_h2(pack_h2(sacc[tn][0], sacc[tn][1]));
            pk1[tn] = ex2_h2(pack_h2(sacc[tn][2], sacc[tn][3]));
        }
        __half2 a0 = __half2half2(__float2half(0.0f));
        __half2 a1 = a0;
        #pragma unroll
        for (int tn = 0; tn < 8; tn++) {
            a0 = __hadd2(a0, *(const __half2*)&pk0[tn]);
            a1 = __hadd2(a1, *(const __half2*)&pk1[tn]);
        }
        float2 f0 = __half22float2(a0);
        float2 f1 = __half22float2(a1);
        float ps0 = f0.x + f0.y;
        float ps1 = f1.x + f1.y;
        ps0 += __shfl_xor_sync(0xFFFFFFFFu, ps0, 1);
        ps0 += __shfl_xor_sync(0xFFFFFFFFu, ps0, 2);
        ps1 += __shfl_xor_sync(0xFFFFFFFFu, ps1, 1);
        ps1 += __shfl_xor_sync(0xFFFFFFFFu, ps1, 2);
        ls0 += ps0;
        ls1 += ps1;

        #pragma unroll
        for (int ks = 0; ks < 4; ks++) {
            unsigned af[4];
            af[0] = pk0[2 * ks];
            af[1] = pk1[2 * ks];
            af[2] = pk0[2 * ks + 1];
            af[3] = pk1[2 * ks + 1];
            #pragma unroll
            for (int tnp = 0; tnp < 4; tnp++) {
                unsigned bf[4];
                ldsm4(bf, vB + kvoff[tnp] + ks * 32);
                mma16(oacc[2 * tnp],     af, bf[0], bf[1]);
                mma16(oacc[2 * tnp + 1], af, bf[2], bf[3]);
            }
        }
        bufc = (bufc == 2) ? 0 : bufc + 1;
    }

    const float inv0 = 1.0f / ls0, inv1 = 1.0f / ls1;
    __half* O0 = Oh + ((size_t)(b * SEQ + ql0 + warp * 16 + lr)) * D_MODEL + h * HEAD_E;
    __half* O1 = O0 + 8 * D_MODEL;
    #pragma unroll
    for (int tn = 0; tn < 8; tn++) {
        const int col = tn * 8 + 2 * lc;
        *(unsigned*)&O0[col] = pack_h2(oacc[tn][0] * inv0, oacc[tn][1] * inv0);
        *(unsigned*)&O1[col] = pack_h2(oacc[tn][2] * inv1, oacc[tn][3] * inv1);
    }
}

// ---------------- LN1: fp32 X + fp16 Y -> fp16 out ---------------------------
__global__ void __launch_bounds__(128)
ln1_kernel(const float* __restrict__ X, const __half* __restrict__ Y,
           const float* __restrict__ g, const float* __restrict__ bta,
           __half* __restrict__ Out16)
{
    __shared__ float red[8];
    const int row = blockIdx.x;
    const int tid = threadIdx.x;
    const int col = tid * 4;

    float4 xv = *(const float4*)&X[(size_t)row * D_MODEL + col];
    uint2  yu = *(const uint2*)&Y[(size_t)row * D_MODEL + col];
    float2 ya = __half22float2(*(const __half2*)&yu.x);
    float2 yb = __half22float2(*(const __half2*)&yu.y);
    float v0 = xv.x + ya.x, v1 = xv.y + ya.y, v2 = xv.z + yb.x, v3 = xv.w + yb.y;

    float sum = v0 + v1 + v2 + v3;
    float sq  = v0 * v0 + v1 * v1 + v2 * v2 + v3 * v3;
    #pragma unroll
    for (int off = 16; off > 0; off >>= 1) {
        sum += __shfl_xor_sync(0xFFFFFFFFu, sum, off);
        sq  += __shfl_xor_sync(0xFFFFFFFFu, sq,  off);
    }
    const int wid  = tid >> 5;
    const int lane = tid & 31;
    if (lane == 0) { red[wid] = sum; red[4 + wid] = sq; }
    __syncthreads();
    sum = red[0] + red[1] + red[2] + red[3];
    sq  = red[4] + red[5] + red[6] + red[7];

    const float mu  = sum * (1.0f / D_MODEL);
    const float var = sq * (1.0f / D_MODEL) - mu * mu;
    const float rst = rsqrtf(var + 1e-5f);

    float4 gv = *(const float4*)&g[col];
    float4 bv = *(const float4*)&bta[col];
    float w0 = (v0 - mu) * rst * gv.x + bv.x;
    float w1 = (v1 - mu) * rst * gv.y + bv.y;
    float w2 = (v2 - mu) * rst * gv.z + bv.z;
    float w3 = (v3 - mu) * rst * gv.w + bv.w;
    *(uint2*)&Out16[(size_t)row * D_MODEL + col] =
        make_uint2(pack_h2(w0, w1), pack_h2(w2, w3));
}

// ---------------- LN2: fp16 X + fp16 Y -> fp32 out ---------------------------
__global__ void __launch_bounds__(128)
ln2_kernel(const __half* __restrict__ X, const __half* __restrict__ Y,
           const float* __restrict__ g, const float* __restrict__ bta,
           float* __restrict__ Out)
{
    __shared__ float red[8];
    const int row = blockIdx.x;
    const int tid = threadIdx.x;
    const int col = tid * 4;

    uint2  xu = *(const uint2*)&X[(size_t)row * D_MODEL + col];
    uint2  yu = *(const uint2*)&Y[(size_t)row * D_MODEL + col];
    float2 xa = __half22float2(*(const __half2*)&xu.x);
    float2 xb = __half22float2(*(const __half2*)&xu.y);
    float2 ya = __half22float2(*(const __half2*)&yu.x);
    float2 yb = __half22float2(*(const __half2*)&yu.y);
    float v0 = xa.x + ya.x, v1 = xa.y + ya.y, v2 = xb.x + yb.x, v3 = xb.y + yb.y;

    float sum = v0 + v1 + v2 + v3;
    float sq  = v0 * v0 + v1 * v1 + v2 * v2 + v3 * v3;
    #pragma unroll
    for (int off = 16; off > 0; off >>= 1) {
        sum += __shfl_xor_sync(0xFFFFFFFFu, sum, off);
        sq  += __shfl_xor_sync(0xFFFFFFFFu, sq,  off);
    }
    const int wid  = tid >> 5;
    const int lane = tid & 31;
    if (lane == 0) { red[wid] = sum; red[4 + wid] = sq; }
    __syncthreads();
    sum = red[0] + red[1] + red[2] + red[3];
    sq  = red[4] + red[5] + red[6] + red[7];

    const float mu  = sum * (1.0f / D_MODEL);
    const float var = sq * (1.0f / D_MODEL) - mu * mu;
    const float rst = rsqrtf(var + 1e-5f);

    float4 gv = *(const float4*)&g[col];
    float4 bv = *(const float4*)&bta[col];
    float4 w;
    w.x = (v0 - mu) * rst * gv.x + bv.x;
    w.y = (v1 - mu) * rst * gv.y + bv.y;
    w.z = (v2 - mu) * rst * gv.z + bv.z;
    w.w = (v3 - mu) * rst * gv.w + bv.w;
    *(float4*)&Out[(size_t)row * D_MODEL + col] = w;
}

// ---------------- launcher --------------------------------------------------
extern "C" void kernel_launch(void* const* d_in, const int* in_sizes, int n_in,
                              void* d_out, int out_size)
{
    const float* x   = (const float*)d_in[0];
    const float* Wq  = (const float*)d_in[1];
    const float* bq  = (const float*)d_in[2];
    const float* Wk  = (const float*)d_in[3];
    const float* bk  = (const float*)d_in[4];
    const float* Wv  = (const float*)d_in[5];
    const float* bv  = (const float*)d_in[6];
    const float* Wo  = (const float*)d_in[7];
    const float* bo  = (const float*)d_in[8];
    const float* W1  = (const float*)d_in[9];
    const float* b1  = (const float*)d_in[10];
    const float* W2  = (const float*)d_in[11];
    const float* b2  = (const float*)d_in[12];
    const float* g1  = (const float*)d_in[13];
    const float* be1 = (const float*)d_in[14];
    const float* g2  = (const float*)d_in[15];
    const float* be2 = (const float*)d_in[16];
    float* out = (float*)d_out;

    __half *xh, *qh, *kh, *vt, *ah, *h16, *x1h, *p16, *f16, *wqkv, *wot, *w1t, *w2t;
    float *bqkv;
    cudaGetSymbolAddress((void**)&xh,   g_xh);
    cudaGetSymbolAddress((void**)&qh,   g_qh);
    cudaGetSymbolAddress((void**)&kh,   g_kh);
    cudaGetSymbolAddress((void**)&vt,   g_vt);
    cudaGetSymbolAddress((void**)&ah,   g_ah);
    cudaGetSymbolAddress((void**)&h16,  g_h16);
    cudaGetSymbolAddress((void**)&x1h,  g_x1h);
    cudaGetSymbolAddress((void**)&p16,  g_p16);
    cudaGetSymbolAddress((void**)&f16,  g_f16);
    cudaGetSymbolAddress((void**)&wqkv, g_wqkv);
    cudaGetSymbolAddress((void**)&wot,  g_wot);
    cudaGetSymbolAddress((void**)&w1t,  g_w1t);
    cudaGetSymbolAddress((void**)&w2t,  g_w2t);
    cudaGetSymbolAddress((void**)&bqkv, g_bqkv);

    cudaFuncSetAttribute((const void*)mma_gemm<0,1>,
                         cudaFuncAttributeMaxDynamicSharedMemorySize, GEMM_SMEM);
    cudaFuncSetAttribute((const void*)mma_gemm<0,3>,
                         cudaFuncAttributeMaxDynamicSharedMemorySize, GEMM_SMEM);
    cudaFuncSetAttribute((const void*)mma_gemm<1,1>,
                         cudaFuncAttributeMaxDynamicSharedMemorySize, GEMM_SMEM);
    cudaFuncSetAttribute((const void*)flash_kernel,
                         cudaFuncAttributeMaxDynamicSharedMemorySize, FLASH_SMEM);

    // ---- prep (single merged launch) ----
    prep_kernel<<<7170, 256>>>(x, Wq, Wk, Wv, Wo, W1, W2, bq, bk, bv,
                               xh, wqkv, wot, w1t, w2t, bqkv);

    // ---- fused QKV projection (k pre-scaled by log2e in epilogue) ----
    mma_gemm<0,3><<<dim3(12, M_ROWS / 128), 256, GEMM_SMEM>>>(
        xh, wqkv, bqkv, qh, kh, vt, D_MODEL, 3 * D_MODEL);

    // ---- flash attention ----
    flash_kernel<<<dim3(SEQ / 128, BATCH * N_HEADS), 256, FLASH_SMEM>>>(qh, kh, vt, ah);

    // ---- output projection (fp16 out) + residual LN1 -> fp16 x1h ----
    mma_gemm<0,1><<<dim3(4, M_ROWS / 128), 256, GEMM_SMEM>>>(
        ah, wot, bo, p16, 0, 0, D_MODEL, D_MODEL);
    ln1_kernel<<<M_ROWS, 128>>>(x, p16, g1, be1, x1h);

    // ---- FFN + residual LN2 (x1h residual, fp32 final out) ----
    mma_gemm<1,1><<<dim3(16, M_ROWS / 128), 256, GEMM_SMEM>>>(
        x1h, w1t, b1, h16, 0, 0, D_MODEL, D_FF);
    mma_gemm<0,1><<<dim3(4, M_ROWS / 128), 256, GEMM_SMEM>>>(
        h16, w2t, b2, f16, 0, 0, D_FF, D_MODEL);
    ln2_kernel<<<M_ROWS, 128>>>(x1h, f16, g2, be2, out);
}